// round 12
// baseline (speedup 1.0000x reference)
#include <cuda_runtime.h>
#include <math.h>

#define B_ 4096
#define T_ 256
#define V_ 16
#define E_ 10
#define H_ 50
#define O_ 16

#define BLOCK_ 256
#define ROWS_PER_BLOCK_ (BLOCK_ / O_)        // 16
#define GRID_ (B_ / ROWS_PER_BLOCK_)         // 256

#define HS_ 51   // sh_h row stride: kills 2-way cross-token bank alias

// sigmoid / tanh via MUFU (EX2 + RCP): ~1e-6 rel error, well under 1e-3 budget.
__device__ __forceinline__ float fast_sigmoid(float x) {
    return __fdividef(1.0f, 1.0f + __expf(-x));
}
__device__ __forceinline__ float fast_tanh(float x) {
    return fmaf(2.0f, __fdividef(1.0f, 1.0f + __expf(-2.0f * x)), -1.0f);
}

__device__ __forceinline__ void copy_f4(float* dst, const float* src, int n,
                                        int tid, int nthreads) {
    const float4* s = reinterpret_cast<const float4*>(src);
    float4* d = reinterpret_cast<float4*>(dst);
    for (int i = tid; i < (n >> 2); i += nthreads) d[i] = s[i];
}

// Only x[b, T-1] matters; output depends solely on the token value in [0,16).
// Converged kernel (proven R10 config): grid=256 x block=256, float4 param
// staging, 16 tokens x 16 lanes phase 1, dual-accumulator phase 2 (stride-2,
// LDS.64-safe: k*H_ offsets are 8B aligned), one coalesced output per thread.
// Wall time sits at the ~8.6us harness replay floor; SM work is ~1.2k cycles.
__global__ __launch_bounds__(BLOCK_, 1)
void dclstm_kernel(const int* __restrict__ x,
                   const float* __restrict__ emb,
                   const float* __restrict__ w1,
                   const float* __restrict__ b1,
                   const float* __restrict__ b2,
                   const float* __restrict__ w_out,
                   const float* __restrict__ b_out,
                   float* __restrict__ out)
{
    __shared__ float s_w1[4 * H_ * E_];   // 2000
    __shared__ float s_b12[4 * H_];       // 200 (b1+b2 fused)
    __shared__ float s_emb[V_ * E_];      // 160
    __shared__ float s_wout[O_ * H_];     // 800
    __shared__ float s_bout[O_];          // 16
    __shared__ float sh_h[V_][HS_];       // 16 x 51 (padded)

    const int tid = threadIdx.x;
    const int k   = tid & 15;             // output channel 0..15
    const int row = blockIdx.x * ROWS_PER_BLOCK_ + (tid >> 4);

    // Issue this row's token load first; hides under param staging + compute.
    const int tok = x[row * T_ + (T_ - 1)];

    // ---- Stage params to smem (coalesced float4) ----
    copy_f4(s_w1,   w1,    4 * H_ * E_, tid, BLOCK_);
    copy_f4(s_emb,  emb,   V_ * E_,     tid, BLOCK_);
    copy_f4(s_wout, w_out, O_ * H_,     tid, BLOCK_);
    copy_f4(s_bout, b_out, O_,          tid, BLOCK_);
    {
        const float4* pb1 = reinterpret_cast<const float4*>(b1);
        const float4* pb2 = reinterpret_cast<const float4*>(b2);
        float4* d = reinterpret_cast<float4*>(s_b12);
        for (int i = tid; i < H_; i += BLOCK_) {    // 50 float4 chunks
            float4 a = pb1[i], b = pb2[i];
            d[i] = make_float4(a.x + b.x, a.y + b.y, a.z + b.z, a.w + b.w);
        }
    }
    __syncthreads();

    // ---- Phase 1: hidden states. 16 tokens x 16 lanes, <=4 units/thread ----
    {
        const int v    = tid >> 4;        // token 0..15
        const int lane = tid & 15;        // 0..15

        float xe[E_];
#pragma unroll
        for (int e = 0; e < E_; ++e) xe[e] = s_emb[v * E_ + e];

#pragma unroll
        for (int rep = 0; rep < 4; ++rep) {
            const int j = lane + rep * 16;
            if (j < H_) {
                float pi = s_b12[j];
                float po = s_b12[100 + j];
                float pg = s_b12[150 + j];
#pragma unroll
                for (int e = 0; e < E_; ++e) {
                    const float xev = xe[e];
                    pi = fmaf(s_w1[(j)       * E_ + e], xev, pi);
                    po = fmaf(s_w1[(100 + j) * E_ + e], xev, po);
                    pg = fmaf(s_w1[(150 + j) * E_ + e], xev, pg);
                }
                const float it = fast_sigmoid(pi);
                const float ot = fast_sigmoid(po);
                const float g  = fast_tanh(pg);
                sh_h[v][j] = ot * fast_tanh(it * g);
            }
        }
    }
    __syncthreads();

    // ---- Phase 2: one output/thread, dual accumulators (LDS.64-safe) ----
    float s0 = s_bout[k], s1 = 0.0f;
#pragma unroll
    for (int j = 0; j < H_; j += 2) {
        s0 = fmaf(sh_h[tok][j],     s_wout[k * H_ + j],     s0);
        s1 = fmaf(sh_h[tok][j + 1], s_wout[k * H_ + j + 1], s1);
    }
    out[blockIdx.x * BLOCK_ + tid] = s0 + s1;   // == out[row*O_ + k], coalesced
}

extern "C" void kernel_launch(void* const* d_in, const int* in_sizes, int n_in,
                              void* d_out, int out_size)
{
    // metadata order: x, emb, w1, b1, w2, b2, w_out, b_out
    const int*   x     = (const int*)  d_in[0];
    const float* emb   = (const float*)d_in[1];
    const float* w1    = (const float*)d_in[2];
    const float* b1    = (const float*)d_in[3];
    // d_in[4] = w2 (unused by the reference)
    const float* b2    = (const float*)d_in[5];
    const float* w_out = (const float*)d_in[6];
    const float* b_out = (const float*)d_in[7];
    float* out = (float*)d_out;

    dclstm_kernel<<<GRID_, BLOCK_>>>(x, emb, w1, b1, b2, w_out, b_out, out);
}

// round 13
// speedup vs baseline: 1.0037x; 1.0037x over previous
#include <cuda_runtime.h>
#include <math.h>

#define B_ 4096
#define T_ 256
#define V_ 16
#define E_ 10
#define H_ 50
#define O_ 16

#define BLOCK_ 256
#define ROWS_PER_BLOCK_ (BLOCK_ / O_)        // 16
#define GRID_ (B_ / ROWS_PER_BLOCK_)         // 256

#define HS_ 51   // sh_h row stride: kills 2-way cross-token bank alias

// sigmoid / tanh via MUFU (EX2 + RCP): ~1e-6 rel error, well under 1e-3 budget.
__device__ __forceinline__ float fast_sigmoid(float x) {
    return __fdividef(1.0f, 1.0f + __expf(-x));
}
__device__ __forceinline__ float fast_tanh(float x) {
    return fmaf(2.0f, __fdividef(1.0f, 1.0f + __expf(-2.0f * x)), -1.0f);
}

__device__ __forceinline__ void copy_f4(float* dst, const float* src, int n,
                                        int tid, int nthreads) {
    const float4* s = reinterpret_cast<const float4*>(src);
    float4* d = reinterpret_cast<float4*>(dst);
    for (int i = tid; i < (n >> 2); i += nthreads) d[i] = s[i];
}

// CONVERGED KERNEL (R12, reproduced twice at 8.67us wall / 7.0us ncu).
//
// Key structural insight: only x[b, T-1] matters (reference takes h_t[:, -1]),
// and the output depends solely on that token value in [0,16) -- so the whole
// problem reduces to a 16-entry token->output[16] table plus a gather.
//
// Layout: grid=256 x block=256. Each block:
//   - issues its 16 rows' token LDGs first (HW-broadcast, latency hidden),
//   - stages the 13.5KB of parameters to smem with coalesced float4 copies
//     (b1+b2 fused on load),
//   - phase 1: 16 tokens x 16 lanes compute the 16x50 hidden matrix
//     (sigmoid/tanh via MUFU, <=4 units/thread),
//   - phase 2: one output float per thread, dual accumulators, LDS.64-safe
//     8B-aligned offsets (LDS.128 at k*200B traps for odd k -- see R11),
//   - one fully-coalesced 1KB store per block (out[row*16+k] == base+tid).
//
// Wall time sits at the ~8.6us harness replay/launch floor; SM critical path
// is ~1.2k cycles and every chip pipe is <7% busy.
__global__ __launch_bounds__(BLOCK_, 1)
void dclstm_kernel(const int* __restrict__ x,
                   const float* __restrict__ emb,
                   const float* __restrict__ w1,
                   const float* __restrict__ b1,
                   const float* __restrict__ b2,
                   const float* __restrict__ w_out,
                   const float* __restrict__ b_out,
                   float* __restrict__ out)
{
    __shared__ float s_w1[4 * H_ * E_];   // 2000
    __shared__ float s_b12[4 * H_];       // 200 (b1+b2 fused)
    __shared__ float s_emb[V_ * E_];      // 160
    __shared__ float s_wout[O_ * H_];     // 800
    __shared__ float s_bout[O_];          // 16
    __shared__ float sh_h[V_][HS_];       // 16 x 51 (padded)

    const int tid = threadIdx.x;
    const int k   = tid & 15;             // output channel 0..15
    const int row = blockIdx.x * ROWS_PER_BLOCK_ + (tid >> 4);

    // Issue this row's token load first; hides under param staging + compute.
    const int tok = x[row * T_ + (T_ - 1)];

    // ---- Stage params to smem (coalesced float4) ----
    copy_f4(s_w1,   w1,    4 * H_ * E_, tid, BLOCK_);
    copy_f4(s_emb,  emb,   V_ * E_,     tid, BLOCK_);
    copy_f4(s_wout, w_out, O_ * H_,     tid, BLOCK_);
    copy_f4(s_bout, b_out, O_,          tid, BLOCK_);
    {
        const float4* pb1 = reinterpret_cast<const float4*>(b1);
        const float4* pb2 = reinterpret_cast<const float4*>(b2);
        float4* d = reinterpret_cast<float4*>(s_b12);
        for (int i = tid; i < H_; i += BLOCK_) {    // 50 float4 chunks
            float4 a = pb1[i], b = pb2[i];
            d[i] = make_float4(a.x + b.x, a.y + b.y, a.z + b.z, a.w + b.w);
        }
    }
    __syncthreads();

    // ---- Phase 1: hidden states. 16 tokens x 16 lanes, <=4 units/thread ----
    {
        const int v    = tid >> 4;        // token 0..15
        const int lane = tid & 15;        // 0..15

        float xe[E_];
#pragma unroll
        for (int e = 0; e < E_; ++e) xe[e] = s_emb[v * E_ + e];

#pragma unroll
        for (int rep = 0; rep < 4; ++rep) {
            const int j = lane + rep * 16;
            if (j < H_) {
                float pi = s_b12[j];
                float po = s_b12[100 + j];
                float pg = s_b12[150 + j];
#pragma unroll
                for (int e = 0; e < E_; ++e) {
                    const float xev = xe[e];
                    pi = fmaf(s_w1[(j)       * E_ + e], xev, pi);
                    po = fmaf(s_w1[(100 + j) * E_ + e], xev, po);
                    pg = fmaf(s_w1[(150 + j) * E_ + e], xev, pg);
                }
                const float it = fast_sigmoid(pi);
                const float ot = fast_sigmoid(po);
                const float g  = fast_tanh(pg);
                sh_h[v][j] = ot * fast_tanh(it * g);
            }
        }
    }
    __syncthreads();

    // ---- Phase 2: one output/thread, dual accumulators (LDS.64-safe) ----
    float s0 = s_bout[k], s1 = 0.0f;
#pragma unroll
    for (int j = 0; j < H_; j += 2) {
        s0 = fmaf(sh_h[tok][j],     s_wout[k * H_ + j],     s0);
        s1 = fmaf(sh_h[tok][j + 1], s_wout[k * H_ + j + 1], s1);
    }
    out[blockIdx.x * BLOCK_ + tid] = s0 + s1;   // == out[row*O_ + k], coalesced
}

extern "C" void kernel_launch(void* const* d_in, const int* in_sizes, int n_in,
                              void* d_out, int out_size)
{
    // metadata order: x, emb, w1, b1, w2, b2, w_out, b_out
    const int*   x     = (const int*)  d_in[0];
    const float* emb   = (const float*)d_in[1];
    const float* w1    = (const float*)d_in[2];
    const float* b1    = (const float*)d_in[3];
    // d_in[4] = w2 (unused by the reference)
    const float* b2    = (const float*)d_in[5];
    const float* w_out = (const float*)d_in[6];
    const float* b_out = (const float*)d_in[7];
    float* out = (float*)d_out;

    dclstm_kernel<<<GRID_, BLOCK_>>>(x, emb, w1, b1, b2, w_out, b_out, out);
}